// round 8
// baseline (speedup 1.0000x reference)
#include <cuda_runtime.h>
#include <cuda_bf16.h>
#include <math.h>

#define NB 65536
#define HALF 32768
#define LH 64
#define GOALC 0.5f
#define MINPC (-1.2f)
#define UTHRESH 0.5f

typedef unsigned long long u64;

// ---- packed f32x2 primitives (single-slot FFMA2/FADD2/FMUL2 on sm_103a) ----
__device__ __forceinline__ u64 pk2(float lo, float hi) {
    u64 r; asm("mov.b64 %0, {%1, %2};" : "=l"(r) : "f"(lo), "f"(hi)); return r;
}
__device__ __forceinline__ void upk2(u64 v, float& lo, float& hi) {
    asm("mov.b64 {%0, %1}, %2;" : "=f"(lo), "=f"(hi) : "l"(v));
}
__device__ __forceinline__ u64 mul2(u64 a, u64 b) {
    u64 r; asm("mul.rn.f32x2 %0, %1, %2;" : "=l"(r) : "l"(a), "l"(b)); return r;
}
__device__ __forceinline__ u64 fma2(u64 a, u64 b, u64 c) {
    u64 r; asm("fma.rn.f32x2 %0, %1, %2, %3;" : "=l"(r) : "l"(a), "l"(b), "l"(c)); return r;
}
__device__ __forceinline__ u64 add2(u64 a, u64 b) {
    u64 r; asm("add.rn.f32x2 %0, %1, %2;" : "=l"(r) : "l"(a), "l"(b)); return r;
}

// XLA / Eigen rational tanh approximation for f32 (matches reference lowering).
__device__ __forceinline__ float xla_tanh(float xin) {
    const float x = fminf(fmaxf(xin, -7.99881172180175781f), 7.99881172180175781f);
    const float x2 = __fmul_rn(x, x);
    float p = __fmaf_rn(x2, -2.76076847742355e-16f, 2.00018790482477e-13f);
    p = __fmaf_rn(x2, p, -8.60467152213735e-11f);
    p = __fmaf_rn(x2, p, 5.12229709037114e-08f);
    p = __fmaf_rn(x2, p, 1.48572235717979e-05f);
    p = __fmaf_rn(x2, p, 6.37261928875436e-04f);
    p = __fmaf_rn(x2, p, 4.89352455891786e-03f);
    p = __fmul_rn(x, p);
    float q = __fmaf_rn(x2, 1.19825839466702e-06f, 1.18534705686654e-04f);
    q = __fmaf_rn(x2, q, 2.26843463243900e-03f);
    q = __fmaf_rn(x2, q, 4.89352518554385e-03f);
    const float r = __fdiv_rn(p, q);
    return (fabsf(xin) < 0.0004f) ? xin : r;
}

// fp32 cos (|x| <= ~3.8), Cody-Waite with residual carry, ~1-1.5 ulp.
__device__ __forceinline__ float cos_cw(float x) {
    const float kf = rintf(__fmul_rn(x, 0.63661977236758134f));
    const int k = (int)kf;
    const float DP1 = 1.5703125f;
    const float DP2 = 4.837512969970703125e-4f;
    const float DP3 = 7.549789948768648e-8f;
    const float t  = __fmaf_rn(-kf, DP1, x);
    const float rh = __fmaf_rn(-kf, DP2, t);
    float rl = __fsub_rn(__fsub_rn(t, rh), __fmul_rn(kf, DP2));
    rl = __fmaf_rn(-kf, DP3, rl);
    const float z = __fmul_rn(rh, rh);

    float pc = __fmaf_rn(z, 2.443315711809948e-5f, -1.388731625493765e-3f);
    pc = __fmaf_rn(z, pc, 4.166664568298827e-2f);
    float c = __fmaf_rn(z, -0.5f, 1.0f);
    c = __fmaf_rn(__fmul_rn(z, z), pc, c);
    c = __fmaf_rn(-rl, rh, c);

    float ps = __fmaf_rn(z, -1.9515295891e-4f, 8.3321608736e-3f);
    ps = __fmaf_rn(z, ps, -1.6666654611e-1f);
    float s = __fmaf_rn(__fmul_rn(rh, z), ps, rl);
    s = __fadd_rn(rh, s);

    const int q = k & 3;
    float r = (q & 1) ? s : c;
    if (q == 1 || q == 2) r = -r;
    return r;
}

// Epilogue from pre-activation to new state (bit-identical to R5/R6).
__device__ __forceinline__ void epilogue(float pre, float pr, float vr,
                                         float& pn, float& vn, float& un, float& an) {
    an = xla_tanh(pre);
    un = (an <= UTHRESH) ? -1.0f : 1.0f;
    const float c = cos_cw(__fmul_rn(3.0f, pr));
    vn = __fsub_rn(__fadd_rn(vr, __fmul_rn(un, 0.0015f)), __fmul_rn(0.0025f, c));
    pn = __fadd_rn(pr, vn);
}

// Shared weight layout (all broadcast-packed, conflict-free):
//   wA[j]  = { {W1[0][j],W1[0][j]}, {W1[1][j],W1[1][j]} }
//   wZ[k]  = { {W2[2k]/2}x2 , {W2[2k+1]/2}x2 }   (halving is exact)
//   wB[k]  = { {b1[2k]}x2  , {b1[2k+1]}x2 }
template<bool B1_ZERO>
__device__ __forceinline__ void run_pair(
    const ulonglong2* __restrict__ wA,
    const ulonglong2* __restrict__ wZ,
    const ulonglong2* __restrict__ wB,
    float bias2, int n,
    float& pA, float& vA, float& uA, float& aA,
    float& pB, float& vB, float& uB, float& aB)
{
    const u64 ABSM = 0x7FFFFFFF7FFFFFFFULL;
    for (int t = 0; t < n; ++t) {
        const bool actA = (pA <= GOALC);
        const bool actB = (pB <= GOALC);
        if (!(actA || actB)) break;   // inactive is absorbing

        const bool rsA = (pA <= MINPC);
        const float prA = rsA ? MINPC : pA;
        const float vrA = rsA ? 0.0f : vA;
        const bool rsB = (pB <= MINPC);
        const float prB = rsB ? MINPC : pB;
        const float vrB = rsB ? 0.0f : vB;

        const u64 p2 = pk2(prA, prB);
        const u64 v2 = pk2(vrA, vrB);

        // 8 packed accumulator lanes; lane l holds {saA[l], saB[l]}.
        // Per-unit contribution is bit-exact vs R6:
        //   relu(d)*wz + acc  ==  fma(d+|d|, wz/2, acc)   (single rounding)
        u64 s0 = 0, s1 = 0, s2 = 0, s3 = 0, s4 = 0, s5 = 0, s6 = 0, s7 = 0;
        #pragma unroll
        for (int k = 0; k < LH / 2; ++k) {
            const ulonglong2 a0 = wA[2 * k];
            const ulonglong2 a1 = wA[2 * k + 1];
            const ulonglong2 zz = wZ[k];

            u64 d0 = fma2(v2, a0.y, mul2(p2, a0.x));
            u64 d1 = fma2(v2, a1.y, mul2(p2, a1.x));
            if (!B1_ZERO) {
                const ulonglong2 bb = wB[k];
                d0 = add2(d0, bb.x);
                d1 = add2(d1, bb.y);
            }
            const u64 r0 = add2(d0, d0 & ABSM);   // 2*relu(d0), exact
            const u64 r1 = add2(d1, d1 & ABSM);

            const int l0 = (2 * k) & 7, l1 = (2 * k + 1) & 7;
            u64& S0 = (l0 == 0) ? s0 : (l0 == 2) ? s2 : (l0 == 4) ? s4 : s6;
            u64& S1 = (l1 == 1) ? s1 : (l1 == 3) ? s3 : (l1 == 5) ? s5 : s7;
            S0 = fma2(r0, zz.x, S0);
            S1 = fma2(r1, zz.y, S1);
        }

        // unpack lanes and do R6's exact rn merge tree per agent
        float a0f, b0f, a1f, b1f, a2f, b2f, a3f, b3f, a4f, b4f, a5f, b5f, a6f, b6f, a7f, b7f;
        upk2(s0, a0f, b0f); upk2(s1, a1f, b1f); upk2(s2, a2f, b2f); upk2(s3, a3f, b3f);
        upk2(s4, a4f, b4f); upk2(s5, a5f, b5f); upk2(s6, a6f, b6f); upk2(s7, a7f, b7f);

        const float dotA =
            __fadd_rn(__fadd_rn(__fadd_rn(a0f, a1f), __fadd_rn(a2f, a3f)),
                      __fadd_rn(__fadd_rn(a4f, a5f), __fadd_rn(a6f, a7f)));
        const float dotB =
            __fadd_rn(__fadd_rn(__fadd_rn(b0f, b1f), __fadd_rn(b2f, b3f)),
                      __fadd_rn(__fadd_rn(b4f, b5f), __fadd_rn(b6f, b7f)));
        const float preA = __fadd_rn(dotA, bias2);
        const float preB = __fadd_rn(dotB, bias2);

        float pnA, vnA, unA, anA, pnB, vnB, unB, anB;
        epilogue(preA, prA, vrA, pnA, vnA, unA, anA);
        epilogue(preB, prB, vrB, pnB, vnB, unB, anB);

        if (actA) { pA = pnA; vA = vnA; uA = unA; aA = anA; }
        if (actB) { pB = pnB; vB = vnB; uB = unB; aB = anB; }
    }
}

__global__ __launch_bounds__(32)   // 1 warp/block, 1024 blocks -> finest balance
void mc_kernel(const float4* __restrict__ x,
               const float* __restrict__ W1,
               const float* __restrict__ b1,
               const float* __restrict__ W2,
               const float* __restrict__ b2,
               const int* __restrict__ n_steps,
               float4* __restrict__ out)
{
    __shared__ ulonglong2 wA[LH];
    __shared__ ulonglong2 wZ[LH / 2];
    __shared__ ulonglong2 wB[LH / 2];

    const int tid = threadIdx.x;   // 0..31, handles units 2*tid, 2*tid+1
    const int j0 = 2 * tid, j1 = 2 * tid + 1;
    const float wx0 = W1[j0], wy0 = W1[LH + j0];
    const float wx1 = W1[j1], wy1 = W1[LH + j1];
    const float b0v = b1[j0], b1v = b1[j1];
    const float zh0 = __fmul_rn(0.5f, W2[j0]);   // exact scaling
    const float zh1 = __fmul_rn(0.5f, W2[j1]);
    wA[j0] = make_ulonglong2(pk2(wx0, wx0), pk2(wy0, wy0));
    wA[j1] = make_ulonglong2(pk2(wx1, wx1), pk2(wy1, wy1));
    wZ[tid] = make_ulonglong2(pk2(zh0, zh0), pk2(zh1, zh1));
    wB[tid] = make_ulonglong2(pk2(b0v, b0v), pk2(b1v, b1v));
    const int b1_zero = __syncthreads_and(
        (__float_as_uint(b0v) == 0u) && (__float_as_uint(b1v) == 0u));

    const float bias2 = b2[0];
    const int n = n_steps ? n_steps[0] : 64;

    const int iA = blockIdx.x * blockDim.x + tid;   // agents [0, 32768)
    const int iB = iA + HALF;                       // agents [32768, 65536)

    const float4 sA = x[iA];
    const float4 sB = x[iB];
    float pA = sA.x, vA = sA.y, uA = sA.z, aA = sA.w;
    float pB = sB.x, vB = sB.y, uB = sB.z, aB = sB.w;

    if (b1_zero) run_pair<true >(wA, wZ, wB, bias2, n, pA, vA, uA, aA, pB, vB, uB, aB);
    else         run_pair<false>(wA, wZ, wB, bias2, n, pA, vA, uA, aA, pB, vB, uB, aB);

    out[iA] = make_float4(pA, vA, uA, aA);
    out[iB] = make_float4(pB, vB, uB, aB);
}

extern "C" void kernel_launch(void* const* d_in, const int* in_sizes, int n_in,
                              void* d_out, int out_size) {
    const float* x  = (const float*)d_in[0];
    const float* W1 = (const float*)d_in[1];
    const float* b1 = (const float*)d_in[2];
    const float* W2 = (const float*)d_in[3];
    const float* b2 = (const float*)d_in[4];
    const int* ns   = (n_in >= 6) ? (const int*)d_in[5] : nullptr;

    mc_kernel<<<HALF / 32, 32>>>((const float4*)x, W1, b1, W2, b2, ns,
                                 (float4*)d_out);
}

// round 9
// speedup vs baseline: 1.7469x; 1.7469x over previous
#include <cuda_runtime.h>
#include <cuda_bf16.h>
#include <math.h>

#define NB 65536
#define HALF 32768
#define LH 64
#define GOALC 0.5f
#define MINPC (-1.2f)
#define UTHRESH 0.5f

typedef unsigned long long u64;

// ---- packed f32x2 primitives (single-slot FFMA2/FADD2/FMUL2 on sm_103a) ----
__device__ __forceinline__ u64 pk2(float lo, float hi) {
    u64 r; asm("mov.b64 %0, {%1, %2};" : "=l"(r) : "f"(lo), "f"(hi)); return r;
}
__device__ __forceinline__ void upk2(u64 v, float& lo, float& hi) {
    asm("mov.b64 {%0, %1}, %2;" : "=f"(lo), "=f"(hi) : "l"(v));
}
__device__ __forceinline__ u64 mul2(u64 a, u64 b) {
    u64 r; asm("mul.rn.f32x2 %0, %1, %2;" : "=l"(r) : "l"(a), "l"(b)); return r;
}
__device__ __forceinline__ u64 fma2(u64 a, u64 b, u64 c) {
    u64 r; asm("fma.rn.f32x2 %0, %1, %2, %3;" : "=l"(r) : "l"(a), "l"(b), "l"(c)); return r;
}
__device__ __forceinline__ u64 add2(u64 a, u64 b) {
    u64 r; asm("add.rn.f32x2 %0, %1, %2;" : "=l"(r) : "l"(a), "l"(b)); return r;
}

// XLA / Eigen rational tanh approximation for f32 (matches reference lowering).
__device__ __forceinline__ float xla_tanh(float xin) {
    const float x = fminf(fmaxf(xin, -7.99881172180175781f), 7.99881172180175781f);
    const float x2 = __fmul_rn(x, x);
    float p = __fmaf_rn(x2, -2.76076847742355e-16f, 2.00018790482477e-13f);
    p = __fmaf_rn(x2, p, -8.60467152213735e-11f);
    p = __fmaf_rn(x2, p, 5.12229709037114e-08f);
    p = __fmaf_rn(x2, p, 1.48572235717979e-05f);
    p = __fmaf_rn(x2, p, 6.37261928875436e-04f);
    p = __fmaf_rn(x2, p, 4.89352455891786e-03f);
    p = __fmul_rn(x, p);
    float q = __fmaf_rn(x2, 1.19825839466702e-06f, 1.18534705686654e-04f);
    q = __fmaf_rn(x2, q, 2.26843463243900e-03f);
    q = __fmaf_rn(x2, q, 4.89352518554385e-03f);
    const float r = __fdiv_rn(p, q);
    return (fabsf(xin) < 0.0004f) ? xin : r;
}

// fp32 cos (|x| <= ~3.8), Cody-Waite with residual carry, ~1-1.5 ulp.
__device__ __forceinline__ float cos_cw(float x) {
    const float kf = rintf(__fmul_rn(x, 0.63661977236758134f));
    const int k = (int)kf;
    const float DP1 = 1.5703125f;
    const float DP2 = 4.837512969970703125e-4f;
    const float DP3 = 7.549789948768648e-8f;
    const float t  = __fmaf_rn(-kf, DP1, x);
    const float rh = __fmaf_rn(-kf, DP2, t);
    float rl = __fsub_rn(__fsub_rn(t, rh), __fmul_rn(kf, DP2));
    rl = __fmaf_rn(-kf, DP3, rl);
    const float z = __fmul_rn(rh, rh);

    float pc = __fmaf_rn(z, 2.443315711809948e-5f, -1.388731625493765e-3f);
    pc = __fmaf_rn(z, pc, 4.166664568298827e-2f);
    float c = __fmaf_rn(z, -0.5f, 1.0f);
    c = __fmaf_rn(__fmul_rn(z, z), pc, c);
    c = __fmaf_rn(-rl, rh, c);

    float ps = __fmaf_rn(z, -1.9515295891e-4f, 8.3321608736e-3f);
    ps = __fmaf_rn(z, ps, -1.6666654611e-1f);
    float s = __fmaf_rn(__fmul_rn(rh, z), ps, rl);
    s = __fadd_rn(rh, s);

    const int q = k & 3;
    float r = (q & 1) ? s : c;
    if (q == 1 || q == 2) r = -r;
    return r;
}

// Largest float T in [0.4, 1.0] with xla_tanh(T) <= UTHRESH (bit bisection).
__device__ __forceinline__ float tanh_threshold() {
    unsigned a = __float_as_uint(0.4f);   // xla_tanh(0.4) < 0.5
    unsigned b = __float_as_uint(1.0f);   // xla_tanh(1.0) > 0.5
    while (b - a > 1u) {
        const unsigned m = a + (b - a) / 2u;
        if (xla_tanh(__uint_as_float(m)) <= UTHRESH) a = m; else b = m;
    }
    return __uint_as_float(a);
}

// Shared weight layout (broadcast-packed, conflict-free):
//   wA[j] = { {W1[0][j]}x2, {W1[1][j]}x2 }
//   wZ[k] = { {W2[2k]/2}x2, {W2[2k+1]/2}x2 }   (halving exact)
//   wB[k] = { {b1[2k]}x2 , {b1[2k+1]}x2 }
template<bool B1_ZERO>
__device__ __forceinline__ void run_pair(
    const ulonglong2* __restrict__ wA,
    const ulonglong2* __restrict__ wZ,
    const ulonglong2* __restrict__ wB,
    float bias2, float T, int n,
    float& pA, float& vA, float& uA, float& aA,
    float& pB, float& vB, float& uB, float& aB)
{
    const u64 ABSM = 0x7FFFFFFF7FFFFFFFULL;
    float lastPreA = 0.0f, lastPreB = 0.0f;
    bool tookA = false, tookB = false;

    for (int t = 0; t < n; ++t) {
        const bool actA = (pA <= GOALC);
        const bool actB = (pB <= GOALC);
        if (!(actA || actB)) break;   // inactive is absorbing

        const bool rsA = (pA <= MINPC);
        const float prA = rsA ? MINPC : pA;
        const float vrA = rsA ? 0.0f : vA;
        const bool rsB = (pB <= MINPC);
        const float prB = rsB ? MINPC : pB;
        const float vrB = rsB ? 0.0f : vB;

        const u64 p2 = pk2(prA, prB);
        const u64 v2 = pk2(vrA, vrB);

        // 8 packed accumulator lanes; per-unit contribution bit-exact vs R6:
        //   relu(d)*wz + acc == fma(d+|d|, wz/2, acc)   (single rounding)
        u64 s0 = 0, s1 = 0, s2 = 0, s3 = 0, s4 = 0, s5 = 0, s6 = 0, s7 = 0;
        #pragma unroll 4
        for (int k = 0; k < LH / 2; ++k) {
            const ulonglong2 a0 = wA[2 * k];
            const ulonglong2 a1 = wA[2 * k + 1];
            const ulonglong2 zz = wZ[k];

            u64 d0 = fma2(v2, a0.y, mul2(p2, a0.x));
            u64 d1 = fma2(v2, a1.y, mul2(p2, a1.x));
            if (!B1_ZERO) {
                const ulonglong2 bb = wB[k];
                d0 = add2(d0, bb.x);
                d1 = add2(d1, bb.y);
            }
            const u64 r0 = add2(d0, d0 & ABSM);   // 2*relu, exact
            const u64 r1 = add2(d1, d1 & ABSM);

            const int l0 = (2 * k) & 7, l1 = (2 * k + 1) & 7;
            u64& S0 = (l0 == 0) ? s0 : (l0 == 2) ? s2 : (l0 == 4) ? s4 : s6;
            u64& S1 = (l1 == 1) ? s1 : (l1 == 3) ? s3 : (l1 == 5) ? s5 : s7;
            S0 = fma2(r0, zz.x, S0);
            S1 = fma2(r1, zz.y, S1);
        }

        // packed rn merge tree (per-lane identical to R6's scalar tree)
        const u64 tot = add2(add2(add2(s0, s1), add2(s2, s3)),
                             add2(add2(s4, s5), add2(s6, s7)));
        float dotA, dotB;
        upk2(tot, dotA, dotB);
        const float preA = __fadd_rn(dotA, bias2);
        const float preB = __fadd_rn(dotB, bias2);

        // un via precomputed threshold (== xla_tanh(pre) <= 0.5); tanh deferred
        const float unA = (preA <= T) ? -1.0f : 1.0f;
        const float unB = (preB <= T) ? -1.0f : 1.0f;

        const float cA = cos_cw(__fmul_rn(3.0f, prA));
        const float cB = cos_cw(__fmul_rn(3.0f, prB));
        const float vnA = __fsub_rn(__fadd_rn(vrA, __fmul_rn(unA, 0.0015f)),
                                    __fmul_rn(0.0025f, cA));
        const float vnB = __fsub_rn(__fadd_rn(vrB, __fmul_rn(unB, 0.0015f)),
                                    __fmul_rn(0.0025f, cB));
        const float pnA = __fadd_rn(prA, vnA);
        const float pnB = __fadd_rn(prB, vnB);

        if (actA) { pA = pnA; vA = vnA; uA = unA; lastPreA = preA; tookA = true; }
        if (actB) { pB = pnB; vB = vnB; uB = unB; lastPreB = preB; tookB = true; }
    }

    // a = tanh of the last active step's pre-activation (or initial a)
    if (tookA) aA = xla_tanh(lastPreA);
    if (tookB) aB = xla_tanh(lastPreB);
}

__global__ __launch_bounds__(64)
void mc_kernel(const float4* __restrict__ x,
               const float* __restrict__ W1,
               const float* __restrict__ b1,
               const float* __restrict__ W2,
               const float* __restrict__ b2,
               const int* __restrict__ n_steps,
               float4* __restrict__ out)
{
    __shared__ ulonglong2 wA[LH];
    __shared__ ulonglong2 wZ[LH / 2];
    __shared__ ulonglong2 wB[LH / 2];

    const int tid = threadIdx.x;   // 0..63
    {
        const float wx = W1[tid], wy = W1[LH + tid];
        wA[tid] = make_ulonglong2(pk2(wx, wx), pk2(wy, wy));
    }
    int zok = 1;
    if (tid < LH / 2) {
        const int j0 = 2 * tid, j1 = 2 * tid + 1;
        const float zh0 = __fmul_rn(0.5f, W2[j0]);
        const float zh1 = __fmul_rn(0.5f, W2[j1]);
        const float b0v = b1[j0], b1v = b1[j1];
        wZ[tid] = make_ulonglong2(pk2(zh0, zh0), pk2(zh1, zh1));
        wB[tid] = make_ulonglong2(pk2(b0v, b0v), pk2(b1v, b1v));
        zok = (__float_as_uint(b0v) == 0u) && (__float_as_uint(b1v) == 0u);
    }
    const int b1_zero = __syncthreads_and(zok);

    const float bias2 = b2[0];
    const float T = tanh_threshold();
    const int n = n_steps ? n_steps[0] : 64;

    const int iA = blockIdx.x * blockDim.x + tid;   // agents [0, 32768)
    const int iB = iA + HALF;                       // agents [32768, 65536)

    const float4 sA = x[iA];
    const float4 sB = x[iB];
    float pA = sA.x, vA = sA.y, uA = sA.z, aA = sA.w;
    float pB = sB.x, vB = sB.y, uB = sB.z, aB = sB.w;

    if (b1_zero) run_pair<true >(wA, wZ, wB, bias2, T, n, pA, vA, uA, aA, pB, vB, uB, aB);
    else         run_pair<false>(wA, wZ, wB, bias2, T, n, pA, vA, uA, aA, pB, vB, uB, aB);

    out[iA] = make_float4(pA, vA, uA, aA);
    out[iB] = make_float4(pB, vB, uB, aB);
}

extern "C" void kernel_launch(void* const* d_in, const int* in_sizes, int n_in,
                              void* d_out, int out_size) {
    const float* x  = (const float*)d_in[0];
    const float* W1 = (const float*)d_in[1];
    const float* b1 = (const float*)d_in[2];
    const float* W2 = (const float*)d_in[3];
    const float* b2 = (const float*)d_in[4];
    const int* ns   = (n_in >= 6) ? (const int*)d_in[5] : nullptr;

    mc_kernel<<<HALF / 64, 64>>>((const float4*)x, W1, b1, W2, b2, ns,
                                 (float4*)d_out);
}

// round 11
// speedup vs baseline: 2.3897x; 1.3680x over previous
#include <cuda_runtime.h>
#include <cuda_bf16.h>
#include <math.h>

#define NB 65536
#define HALF 32768
#define LH 64
#define GOALC 0.5f
#define MINPC (-1.2f)
#define UTHRESH 0.5f

typedef unsigned long long u64;

// ---- packed f32x2 primitives (single-slot FFMA2/FADD2/FMUL2 on sm_103a) ----
__device__ __forceinline__ u64 pk2(float lo, float hi) {
    u64 r; asm("mov.b64 %0, {%1, %2};" : "=l"(r) : "f"(lo), "f"(hi)); return r;
}
__device__ __forceinline__ void upk2(u64 v, float& lo, float& hi) {
    asm("mov.b64 {%0, %1}, %2;" : "=f"(lo), "=f"(hi) : "l"(v));
}
__device__ __forceinline__ u64 mul2(u64 a, u64 b) {
    u64 r; asm("mul.rn.f32x2 %0, %1, %2;" : "=l"(r) : "l"(a), "l"(b)); return r;
}
__device__ __forceinline__ u64 fma2(u64 a, u64 b, u64 c) {
    u64 r; asm("fma.rn.f32x2 %0, %1, %2, %3;" : "=l"(r) : "l"(a), "l"(b), "l"(c)); return r;
}
__device__ __forceinline__ u64 add2(u64 a, u64 b) {
    u64 r; asm("add.rn.f32x2 %0, %1, %2;" : "=l"(r) : "l"(a), "l"(b)); return r;
}

// XLA / Eigen rational tanh approximation for f32 (matches reference lowering).
__device__ __forceinline__ float xla_tanh(float xin) {
    const float x = fminf(fmaxf(xin, -7.99881172180175781f), 7.99881172180175781f);
    const float x2 = __fmul_rn(x, x);
    float p = __fmaf_rn(x2, -2.76076847742355e-16f, 2.00018790482477e-13f);
    p = __fmaf_rn(x2, p, -8.60467152213735e-11f);
    p = __fmaf_rn(x2, p, 5.12229709037114e-08f);
    p = __fmaf_rn(x2, p, 1.48572235717979e-05f);
    p = __fmaf_rn(x2, p, 6.37261928875436e-04f);
    p = __fmaf_rn(x2, p, 4.89352455891786e-03f);
    p = __fmul_rn(x, p);
    float q = __fmaf_rn(x2, 1.19825839466702e-06f, 1.18534705686654e-04f);
    q = __fmaf_rn(x2, q, 2.26843463243900e-03f);
    q = __fmaf_rn(x2, q, 4.89352518554385e-03f);
    const float r = __fdiv_rn(p, q);
    return (fabsf(xin) < 0.0004f) ? xin : r;
}

// fp32 cos (|x| <= ~3.8), Cody-Waite with residual carry, ~1-1.5 ulp.
__device__ __forceinline__ float cos_cw(float x) {
    const float kf = rintf(__fmul_rn(x, 0.63661977236758134f));
    const int k = (int)kf;
    const float DP1 = 1.5703125f;
    const float DP2 = 4.837512969970703125e-4f;
    const float DP3 = 7.549789948768648e-8f;
    const float t  = __fmaf_rn(-kf, DP1, x);
    const float rh = __fmaf_rn(-kf, DP2, t);
    float rl = __fsub_rn(__fsub_rn(t, rh), __fmul_rn(kf, DP2));
    rl = __fmaf_rn(-kf, DP3, rl);
    const float z = __fmul_rn(rh, rh);

    float pc = __fmaf_rn(z, 2.443315711809948e-5f, -1.388731625493765e-3f);
    pc = __fmaf_rn(z, pc, 4.166664568298827e-2f);
    float c = __fmaf_rn(z, -0.5f, 1.0f);
    c = __fmaf_rn(__fmul_rn(z, z), pc, c);
    c = __fmaf_rn(-rl, rh, c);

    float ps = __fmaf_rn(z, -1.9515295891e-4f, 8.3321608736e-3f);
    ps = __fmaf_rn(z, ps, -1.6666654611e-1f);
    float s = __fmaf_rn(__fmul_rn(rh, z), ps, rl);
    s = __fadd_rn(rh, s);

    const int q = k & 3;
    float r = (q & 1) ? s : c;
    if (q == 1 || q == 2) r = -r;
    return r;
}

// Largest float T in [0.4, 1.0] with xla_tanh(T) <= UTHRESH (bit bisection).
__device__ __forceinline__ float tanh_threshold() {
    unsigned a = __float_as_uint(0.4f);
    unsigned b = __float_as_uint(1.0f);
    while (b - a > 1u) {
        const unsigned m = a + (b - a) / 2u;
        if (xla_tanh(__uint_as_float(m)) <= UTHRESH) a = m; else b = m;
    }
    return __uint_as_float(a);
}

// Shared weight layout — packed by UNIT PAIRS (no duplication):
//   wxy[m] = { {W1[0][2m], W1[0][2m+1]}, {W1[1][2m], W1[1][2m+1]} }   m=0..31
//   wzh[q] = { {W2[4q]/2, W2[4q+1]/2}, {W2[4q+2]/2, W2[4q+3]/2} }     q=0..15
//   wbb[m] = { b1[2m], b1[2m+1] }
// Unit j accumulates into scalar lane (j mod 8) in increasing-j order ->
// bit-identical to R6's lane assignment and merge tree.
template<bool B1_ZERO>
__device__ __forceinline__ void run_pair(
    const ulonglong2* __restrict__ wxy,
    const ulonglong2* __restrict__ wzh,
    const u64* __restrict__ wbb,
    float bias2, float T, int n,
    float& pA, float& vA, float& uA, float& aA,
    float& pB, float& vB, float& uB, float& aB)
{
    const u64 ABSM = 0x7FFFFFFF7FFFFFFFULL;
    float lastPreA = 0.0f, lastPreB = 0.0f;
    bool tookA = false, tookB = false;

    for (int t = 0; t < n; ++t) {
        const bool actA = (pA <= GOALC);
        const bool actB = (pB <= GOALC);
        if (!(actA || actB)) break;   // inactive is absorbing

        const bool rsA = (pA <= MINPC);
        const float prA = rsA ? MINPC : pA;
        const float vrA = rsA ? 0.0f : vA;
        const bool rsB = (pB <= MINPC);
        const float prB = rsB ? MINPC : pB;
        const float vrB = rsB ? 0.0f : vB;

        const u64 p2A = pk2(prA, prA), v2A = pk2(vrA, vrA);
        const u64 p2B = pk2(prB, prB), v2B = pk2(vrB, vrB);

        // 4 packed accumulators per agent = 8 scalar lanes (R6 mapping)
        u64 SA0 = 0, SA1 = 0, SA2 = 0, SA3 = 0;
        u64 SB0 = 0, SB1 = 0, SB2 = 0, SB3 = 0;
        #pragma unroll
        for (int q = 0; q < LH / 4; ++q) {        // 4 units per iteration
            const ulonglong2 xy0 = wxy[2 * q];     // units 4q, 4q+1
            const ulonglong2 xy1 = wxy[2 * q + 1]; // units 4q+2, 4q+3
            const ulonglong2 zz  = wzh[q];

            u64 dA0 = fma2(v2A, xy0.y, mul2(p2A, xy0.x));
            u64 dA1 = fma2(v2A, xy1.y, mul2(p2A, xy1.x));
            u64 dB0 = fma2(v2B, xy0.y, mul2(p2B, xy0.x));
            u64 dB1 = fma2(v2B, xy1.y, mul2(p2B, xy1.x));
            if (!B1_ZERO) {
                const u64 bb0 = wbb[2 * q], bb1 = wbb[2 * q + 1];
                dA0 = add2(dA0, bb0); dA1 = add2(dA1, bb1);
                dB0 = add2(dB0, bb0); dB1 = add2(dB1, bb1);
            }
            // relu(d)*wz + acc == fma(d+|d|, wz/2, acc), single rounding (exact)
            const u64 rA0 = add2(dA0, dA0 & ABSM);
            const u64 rA1 = add2(dA1, dA1 & ABSM);
            const u64 rB0 = add2(dB0, dB0 & ABSM);
            const u64 rB1 = add2(dB1, dB1 & ABSM);

            if ((q & 1) == 0) {   // units 4q..4q+3 -> lanes 0..3
                SA0 = fma2(rA0, zz.x, SA0); SA1 = fma2(rA1, zz.y, SA1);
                SB0 = fma2(rB0, zz.x, SB0); SB1 = fma2(rB1, zz.y, SB1);
            } else {              // lanes 4..7
                SA2 = fma2(rA0, zz.x, SA2); SA3 = fma2(rA1, zz.y, SA3);
                SB2 = fma2(rB0, zz.x, SB2); SB3 = fma2(rB1, zz.y, SB3);
            }
        }

        // unpack to scalar lanes and apply R6's exact rn merge tree
        float a0, a1, a2, a3, a4, a5, a6, a7;
        float b0, b1f, b2, b3, b4, b5, b6, b7;
        upk2(SA0, a0, a1); upk2(SA1, a2, a3); upk2(SA2, a4, a5); upk2(SA3, a6, a7);
        upk2(SB0, b0, b1f); upk2(SB1, b2, b3); upk2(SB2, b4, b5); upk2(SB3, b6, b7);

        const float dotA =
            __fadd_rn(__fadd_rn(__fadd_rn(a0, a1), __fadd_rn(a2, a3)),
                      __fadd_rn(__fadd_rn(a4, a5), __fadd_rn(a6, a7)));
        const float dotB =
            __fadd_rn(__fadd_rn(__fadd_rn(b0, b1f), __fadd_rn(b2, b3)),
                      __fadd_rn(__fadd_rn(b4, b5), __fadd_rn(b6, b7)));
        const float preA = __fadd_rn(dotA, bias2);
        const float preB = __fadd_rn(dotB, bias2);

        // un via hoisted tanh threshold (validated bit-exact in R9)
        const float unA = (preA <= T) ? -1.0f : 1.0f;
        const float unB = (preB <= T) ? -1.0f : 1.0f;

        const float cA = cos_cw(__fmul_rn(3.0f, prA));
        const float cB = cos_cw(__fmul_rn(3.0f, prB));
        const float vnA = __fsub_rn(__fadd_rn(vrA, __fmul_rn(unA, 0.0015f)),
                                    __fmul_rn(0.0025f, cA));
        const float vnB = __fsub_rn(__fadd_rn(vrB, __fmul_rn(unB, 0.0015f)),
                                    __fmul_rn(0.0025f, cB));
        const float pnA = __fadd_rn(prA, vnA);
        const float pnB = __fadd_rn(prB, vnB);

        if (actA) { pA = pnA; vA = vnA; uA = unA; lastPreA = preA; tookA = true; }
        if (actB) { pB = pnB; vB = vnB; uB = unB; lastPreB = preB; tookB = true; }
    }

    if (tookA) aA = xla_tanh(lastPreA);
    if (tookB) aB = xla_tanh(lastPreB);
}

__global__ __launch_bounds__(64)   // uncapped regs (R6 recipe: deep LDS batching)
void mc_kernel(const float4* __restrict__ x,
               const float* __restrict__ W1,
               const float* __restrict__ b1,
               const float* __restrict__ W2,
               const float* __restrict__ b2,
               const int* __restrict__ n_steps,
               float4* __restrict__ out)
{
    __shared__ ulonglong2 wxy[LH / 2];
    __shared__ ulonglong2 wzh[LH / 4];
    __shared__ u64 wbb[LH / 2];

    const int tid = threadIdx.x;   // 0..63
    int zok = 1;
    if (tid < LH / 2) {
        const int j0 = 2 * tid, j1 = 2 * tid + 1;
        wxy[tid] = make_ulonglong2(pk2(W1[j0], W1[j1]),
                                   pk2(W1[LH + j0], W1[LH + j1]));
        const float bv0 = b1[j0], bv1 = b1[j1];
        wbb[tid] = pk2(bv0, bv1);
        zok = (__float_as_uint(bv0) == 0u) && (__float_as_uint(bv1) == 0u);
    }
    if (tid < LH / 4) {
        const int j = 4 * tid;
        wzh[tid] = make_ulonglong2(
            pk2(__fmul_rn(0.5f, W2[j]),     __fmul_rn(0.5f, W2[j + 1])),
            pk2(__fmul_rn(0.5f, W2[j + 2]), __fmul_rn(0.5f, W2[j + 3])));
    }
    const int b1_zero = __syncthreads_and(zok);

    const float bias2 = b2[0];
    const float T = tanh_threshold();
    const int n = n_steps ? n_steps[0] : 64;

    const int iA = blockIdx.x * blockDim.x + tid;   // agents [0, 32768)
    const int iB = iA + HALF;                       // agents [32768, 65536)

    const float4 sA = x[iA];
    const float4 sB = x[iB];
    float pA = sA.x, vA = sA.y, uA = sA.z, aA = sA.w;
    float pB = sB.x, vB = sB.y, uB = sB.z, aB = sB.w;

    if (b1_zero) run_pair<true >(wxy, wzh, wbb, bias2, T, n, pA, vA, uA, aA, pB, vB, uB, aB);
    else         run_pair<false>(wxy, wzh, wbb, bias2, T, n, pA, vA, uA, aA, pB, vB, uB, aB);

    out[iA] = make_float4(pA, vA, uA, aA);
    out[iB] = make_float4(pB, vB, uB, aB);
}

extern "C" void kernel_launch(void* const* d_in, const int* in_sizes, int n_in,
                              void* d_out, int out_size) {
    const float* x  = (const float*)d_in[0];
    const float* W1 = (const float*)d_in[1];
    const float* b1 = (const float*)d_in[2];
    const float* W2 = (const float*)d_in[3];
    const float* b2 = (const float*)d_in[4];
    const int* ns   = (n_in >= 6) ? (const int*)d_in[5] : nullptr;

    mc_kernel<<<HALF / 64, 64>>>((const float4*)x, W1, b1, W2, b2, ns,
                                 (float4*)d_out);
}